// round 17
// baseline (speedup 1.0000x reference)
#include <cuda_runtime.h>
#include <cuda_fp16.h>
#include <math.h>
#include <stdint.h>

#define Bb 4
#define Tt 2048
#define Cc 1024
#define Hh 16
#define Dd 64
#define BTC (Bb * Tt * Cc)

// Scratch (no cudaMalloc allowed) — all-half dataflow
__device__ __half g_x16[BTC];
__device__ __half g_wqkvT[3 * Cc * Cc];
__device__ __half g_woutT[Cc * Cc];
__device__ __half g_qh[BTC];   // q roped+scaled  [b,h,t,d]
__device__ __half g_kh[BTC];   // k roped         [b,h,t,d]
__device__ __half g_vt[BTC];   // v transposed    [b,h,d,t]
__device__ __half g_att16[BTC];
__device__ float g_rope[Tt * 64];

__device__ __forceinline__ void cp16(uint32_t saddr, const void* gaddr) {
    asm volatile("cp.async.cg.shared.global [%0], [%1], 16;\n" ::"r"(saddr), "l"(gaddr));
}

#define LDSM_X4(r0, r1, r2, r3, addr)                                            \
    asm volatile("ldmatrix.sync.aligned.m8n8.x4.shared.b16 {%0,%1,%2,%3}, [%4];" \
                 : "=r"(r0), "=r"(r1), "=r"(r2), "=r"(r3)                        \
                 : "r"(addr))

// ---------------------------------------------------------------------------
__global__ __launch_bounds__(256) void f32_to_f16(const float* __restrict__ in,
                                                  __half* __restrict__ out, int n4) {
    int i = blockIdx.x * blockDim.x + threadIdx.x;
    if (i < n4) {
        float4 v = ((const float4*)in)[i];
        ((__half2*)out)[2 * i] = __floats2half2_rn(v.x, v.y);
        ((__half2*)out)[2 * i + 1] = __floats2half2_rn(v.z, v.w);
    }
}

// ---------------------------------------------------------------------------
__global__ __launch_bounds__(256) void transpose_to_half(const float* __restrict__ in,
                                                         __half* __restrict__ out,
                                                         int K, int N) {
    __shared__ float tile[32][33];
    int k0 = blockIdx.y * 32, n0 = blockIdx.x * 32;
#pragma unroll
    for (int r = 0; r < 4; r++) {
        int k = threadIdx.y + r * 8;
        tile[k][threadIdx.x] = in[(size_t)(k0 + k) * N + n0 + threadIdx.x];
    }
    __syncthreads();
#pragma unroll
    for (int r = 0; r < 4; r++) {
        int n = threadIdx.y + r * 8;
        out[(size_t)(n0 + n) * K + k0 + threadIdx.x] =
            __float2half_rn(tile[threadIdx.x][n]);
    }
}

// ---------------------------------------------------------------------------
__global__ __launch_bounds__(256) void rope_table_k(float* __restrict__ tab) {
    int idx = blockIdx.x * 256 + threadIdx.x;
    int t = idx >> 5, i = idx & 31;
    double invf = exp2(-(double)i * (13.287712379549449 / 32.0)); // 10000^(-i/32)
    double a = (double)t * invf;
    double r = a - rint(a * 0.15915494309189535) * 6.283185307179586;
    float s, c;
    sincosf((float)r, &s, &c);
    tab[t * 64 + 2 * i] = c;
    tab[t * 64 + 2 * i + 1] = s;
}

// ---------------------------------------------------------------------------
// fp16 GEMM with ldmatrix fragment loads.
// EPI=0: plain fp32 output to Cm.
// EPI=2: fused qkv epilogue — RoPE on q/k (fp32, pre-rounding), scatter to
//        qh/kh [b,h,t,d] and vt [b,h,d,t]. Section (q/k/v) uniform per CTA.
// ---------------------------------------------------------------------------
#define HSTAGES 4
#define HKT 32
#define HROW 40
#define HA_H (128 * HROW)
#define HSTAGE_H (2 * HA_H)
#define HGEMM_SMEM (HSTAGES * HSTAGE_H * 2)

template <int EPI>
__global__ __launch_bounds__(256, 2) void hgemm(const __half* __restrict__ A,
                                                const __half* __restrict__ Bt,
                                                float* __restrict__ Cm,
                                                __half* __restrict__ qh,
                                                __half* __restrict__ kh,
                                                __half* __restrict__ vt,
                                                const float* __restrict__ tab,
                                                int N, int K) {
    extern __shared__ __half hsm[];
    const int tid = threadIdx.x;
    const int warp = tid >> 5, lane = tid & 31;
    const int wm = warp & 1, wn = warp >> 1;
    const int g = lane >> 2, t = lane & 3;
    const size_t m0 = (size_t)blockIdx.y * 128;
    const int n0 = blockIdx.x * 128;
    const int NT = K / HKT;

    const int l_row = tid >> 1;
    const int l_c = tid & 1;
    const __half* Ag = A + (m0 + l_row) * (size_t)K;
    const __half* Bg = Bt + (size_t)(n0 + l_row) * K;
    const uint32_t sb = (uint32_t)__cvta_generic_to_shared(hsm);

    const int a_off = (lane & 15) * HROW + (lane >> 4) * 8;
    const int b_off = (((lane >> 4) & 1) * 8 + (lane & 7)) * HROW + ((lane >> 3) & 1) * 8;

#define H_ISSUE(kt)                                                             \
    do {                                                                        \
        int s_ = (kt) & (HSTAGES - 1);                                          \
        uint32_t as_ = sb + (s_ * HSTAGE_H + l_row * HROW) * 2;                 \
        uint32_t bs_ = as_ + HA_H * 2;                                          \
        const __half* ag_ = Ag + (kt)*HKT;                                      \
        const __half* bg_ = Bg + (kt)*HKT;                                      \
        cp16(as_ + l_c * 16, ag_ + l_c * 8);                                    \
        cp16(as_ + (l_c + 2) * 16, ag_ + (l_c + 2) * 8);                        \
        cp16(bs_ + l_c * 16, bg_ + l_c * 8);                                    \
        cp16(bs_ + (l_c + 2) * 16, bg_ + (l_c + 2) * 8);                        \
    } while (0)

    H_ISSUE(0);
    asm volatile("cp.async.commit_group;\n");
    H_ISSUE(1);
    asm volatile("cp.async.commit_group;\n");
    H_ISSUE(2);
    asm volatile("cp.async.commit_group;\n");

    float acc[4][4][4];
#pragma unroll
    for (int i = 0; i < 4; i++)
#pragma unroll
        for (int j = 0; j < 4; j++)
#pragma unroll
            for (int r = 0; r < 4; r++) acc[i][j][r] = 0.f;

    for (int kt = 0; kt < NT; kt++) {
        asm volatile("cp.async.wait_group %0;\n" ::"n"(2));
        __syncthreads();

        if (kt + 3 < NT) H_ISSUE(kt + 3);
        asm volatile("cp.async.commit_group;\n");

        const uint32_t As = sb + ((kt & (HSTAGES - 1)) * HSTAGE_H) * 2;
        const uint32_t Bs = As + HA_H * 2;

#pragma unroll
        for (int s16 = 0; s16 < 32; s16 += 16) {
            uint32_t af[4][4], bf[4][2];
#pragma unroll
            for (int i = 0; i < 4; i++) {
                uint32_t addr = As + ((wm * 64 + i * 16) * HROW + s16 + a_off) * 2;
                LDSM_X4(af[i][0], af[i][1], af[i][2], af[i][3], addr);
            }
#pragma unroll
            for (int jp = 0; jp < 2; jp++) {
                uint32_t addr = Bs + ((wn * 32 + jp * 16) * HROW + s16 + b_off) * 2;
                LDSM_X4(bf[2 * jp][0], bf[2 * jp][1], bf[2 * jp + 1][0],
                        bf[2 * jp + 1][1], addr);
            }
#pragma unroll
            for (int i = 0; i < 4; i++)
#pragma unroll
                for (int j = 0; j < 4; j++) {
                    asm volatile(
                        "mma.sync.aligned.m16n8k16.row.col.f32.f16.f16.f32 "
                        "{%0,%1,%2,%3}, {%4,%5,%6,%7}, {%8,%9}, {%0,%1,%2,%3};"
                        : "+f"(acc[i][j][0]), "+f"(acc[i][j][1]),
                          "+f"(acc[i][j][2]), "+f"(acc[i][j][3])
                        : "r"(af[i][0]), "r"(af[i][1]), "r"(af[i][2]), "r"(af[i][3]),
                          "r"(bf[j][0]), "r"(bf[j][1]));
                }
        }
    }

    if (EPI == 0) {
#pragma unroll
        for (int i = 0; i < 4; i++)
#pragma unroll
            for (int j = 0; j < 4; j++) {
                size_t row = m0 + wm * 64 + i * 16 + g;
                int col = n0 + wn * 32 + j * 8 + 2 * t;
                *(float2*)(Cm + row * N + col) =
                    make_float2(acc[i][j][0], acc[i][j][1]);
                *(float2*)(Cm + (row + 8) * N + col) =
                    make_float2(acc[i][j][2], acc[i][j][3]);
            }
    } else {
        // Fused qkv epilogue. sec uniform per CTA (N-tiles don't straddle 1024s).
        const int sec = n0 >> 10;
#pragma unroll
        for (int i = 0; i < 4; i++) {
            const int mtok = (int)m0 + wm * 64 + i * 16 + g;  // and mtok+8
            const int b = mtok >> 11;
            const int t0 = mtok & (Tt - 1);                   // t1 = t0 + 8 (same b)
#pragma unroll
            for (int j = 0; j < 4; j++) {
                const int col = n0 + wn * 32 + j * 8 + 2 * t;
                const int h = (col >> 6) & 15;
                const int d = col & 63;                        // even
                const int bh = b * 16 + h;
                if (sec == 2) {
                    // v: transpose to [b,h,d,t]
                    __half* vb = vt + ((size_t)bh * 64 + d) * Tt + t0;
                    vb[0] = __float2half_rn(acc[i][j][0]);
                    vb[Tt] = __float2half_rn(acc[i][j][1]);
                    vb[8] = __float2half_rn(acc[i][j][2]);
                    vb[Tt + 8] = __float2half_rn(acc[i][j][3]);
                } else {
                    float2 cs0 = *(const float2*)(tab + t0 * 64 + d);
                    float2 cs1 = *(const float2*)(tab + (t0 + 8) * 64 + d);
                    float r00 = acc[i][j][0] * cs0.x - acc[i][j][1] * cs0.y;
                    float r01 = acc[i][j][1] * cs0.x + acc[i][j][0] * cs0.y;
                    float r10 = acc[i][j][2] * cs1.x - acc[i][j][3] * cs1.y;
                    float r11 = acc[i][j][3] * cs1.x + acc[i][j][2] * cs1.y;
                    size_t o0 = ((size_t)bh * Tt + t0) * 64 + d;
                    if (sec == 0) {
                        *(__half2*)(qh + o0) =
                            __floats2half2_rn(r00 * 0.125f, r01 * 0.125f);
                        *(__half2*)(qh + o0 + 8 * 64) =
                            __floats2half2_rn(r10 * 0.125f, r11 * 0.125f);
                    } else {
                        *(__half2*)(kh + o0) = __floats2half2_rn(r00, r01);
                        *(__half2*)(kh + o0 + 8 * 64) = __floats2half2_rn(r10, r11);
                    }
                }
            }
        }
    }
#undef H_ISSUE
}

// ---------------------------------------------------------------------------
// flash16 with ldmatrix (unchanged from R10; att16 out for GEMM2)
// ---------------------------------------------------------------------------
#define QS_H 72
#define FL_SMEM ((9216 + 2 * 9216) * 2)

__global__ __launch_bounds__(256, 2) void flash16(const __half* __restrict__ q16,
                                                  const __half* __restrict__ k16,
                                                  const __half* __restrict__ v16t,
                                                  __half* __restrict__ att) {
    extern __shared__ __half hs[];
    const int iq = gridDim.x - 1 - blockIdx.x;
    const int bh = blockIdx.y;
    const int b = bh >> 4, h = bh & 15;
    const int tid = threadIdx.x;
    const int w = tid >> 5, lane = tid & 31;
    const int g = lane >> 2, t = lane & 3;
    const int wr = w * 16;
    const size_t tbase = (size_t)bh * Tt;
    const uint32_t sb = (uint32_t)__cvta_generic_to_shared(hs);
    const int jmax = 2 * iq + 1;

    const int a_off = (lane & 15) * QS_H + (lane >> 4) * 8;
    const int b_off = (((lane >> 4) & 1) * 8 + (lane & 7)) * QS_H + ((lane >> 3) & 1) * 8;

#define ISSUE_KV(jt, s)                                                          \
    do {                                                                         \
        int row_ = tid >> 2;                                                     \
        int cb_ = tid & 3;                                                       \
        const __half* gk_ = k16 + (tbase + (jt)*64 + row_) * 64;                 \
        const __half* gv_ = v16t + ((size_t)bh * 64 + row_) * Tt + (jt)*64;      \
        uint32_t sk_ = sb + (9216 + (s)*9216 + row_ * QS_H) * 2;                 \
        uint32_t sv_ = sk_ + 4608 * 2;                                           \
        cp16(sk_ + cb_ * 16, gk_ + cb_ * 8);                                     \
        cp16(sk_ + (cb_ + 4) * 16, gk_ + (cb_ + 4) * 8);                         \
        cp16(sv_ + cb_ * 16, gv_ + cb_ * 8);                                     \
        cp16(sv_ + (cb_ + 4) * 16, gv_ + (cb_ + 4) * 8);                         \
    } while (0)

    {
        int row = tid >> 1;
        int cb = tid & 1;
        const __half* gq = q16 + (tbase + iq * 128 + row) * 64;
        uint32_t sq = sb + (row * QS_H) * 2;
#pragma unroll
        for (int c = cb; c < 8; c += 2) cp16(sq + c * 16, gq + c * 8);
    }
    ISSUE_KV(0, 0);
    asm volatile("cp.async.commit_group;\n");

    float oacc[8][4];
    float m0 = -1e30f, m1 = -1e30f, l0 = 0.f, l1 = 0.f;
#pragma unroll
    for (int ds = 0; ds < 8; ds++)
#pragma unroll
        for (int r = 0; r < 4; r++) oacc[ds][r] = 0.f;

    uint32_t qf[4][4];
    bool qf_loaded = false;

    for (int jt = 0; jt <= jmax; jt++) {
        if (jt + 1 <= jmax) ISSUE_KV(jt + 1, (jt + 1) & 1);
        asm volatile("cp.async.commit_group;\n");
        asm volatile("cp.async.wait_group %0;\n" ::"n"(1));
        __syncthreads();

        if (!qf_loaded) {
            qf_loaded = true;
#pragma unroll
            for (int kc = 0; kc < 4; kc++) {
                uint32_t addr = sb + (wr * QS_H + kc * 16 + a_off) * 2;
                LDSM_X4(qf[kc][0], qf[kc][1], qf[kc][2], qf[kc][3], addr);
            }
        }

        const uint32_t Ks = sb + (9216 + (jt & 1) * 9216) * 2;
        const uint32_t Vs = Ks + 4608 * 2;

        float sa[8][4];
#pragma unroll
        for (int ns = 0; ns < 8; ns++)
#pragma unroll
            for (int r = 0; r < 4; r++) sa[ns][r] = 0.f;

#pragma unroll
        for (int kc = 0; kc < 4; kc++)
#pragma unroll
            for (int ns2 = 0; ns2 < 4; ns2++) {
                uint32_t kb0, kb1, kb2, kb3;
                uint32_t addr = Ks + (ns2 * 16 * QS_H + kc * 16 + b_off) * 2;
                LDSM_X4(kb0, kb1, kb2, kb3, addr);
                asm volatile(
                    "mma.sync.aligned.m16n8k16.row.col.f32.f16.f16.f32 "
                    "{%0,%1,%2,%3}, {%4,%5,%6,%7}, {%8,%9}, {%0,%1,%2,%3};"
                    : "+f"(sa[2 * ns2][0]), "+f"(sa[2 * ns2][1]),
                      "+f"(sa[2 * ns2][2]), "+f"(sa[2 * ns2][3])
                    : "r"(qf[kc][0]), "r"(qf[kc][1]), "r"(qf[kc][2]), "r"(qf[kc][3]),
                      "r"(kb0), "r"(kb1));
                asm volatile(
                    "mma.sync.aligned.m16n8k16.row.col.f32.f16.f16.f32 "
                    "{%0,%1,%2,%3}, {%4,%5,%6,%7}, {%8,%9}, {%0,%1,%2,%3};"
                    : "+f"(sa[2 * ns2 + 1][0]), "+f"(sa[2 * ns2 + 1][1]),
                      "+f"(sa[2 * ns2 + 1][2]), "+f"(sa[2 * ns2 + 1][3])
                    : "r"(qf[kc][0]), "r"(qf[kc][1]), "r"(qf[kc][2]), "r"(qf[kc][3]),
                      "r"(kb2), "r"(kb3));
            }

        if (jt >= 2 * iq) {
            const int row0 = iq * 128 + wr + g;
            const int row1 = row0 + 8;
#pragma unroll
            for (int ns = 0; ns < 8; ns++) {
                int c0 = jt * 64 + ns * 8 + 2 * t;
                if (c0 > row0) sa[ns][0] = -1e30f;
                if (c0 + 1 > row0) sa[ns][1] = -1e30f;
                if (c0 > row1) sa[ns][2] = -1e30f;
                if (c0 + 1 > row1) sa[ns][3] = -1e30f;
            }
        }

        {
            float mx0 = -1e30f, mx1 = -1e30f;
#pragma unroll
            for (int ns = 0; ns < 8; ns++) {
                mx0 = fmaxf(mx0, fmaxf(sa[ns][0], sa[ns][1]));
                mx1 = fmaxf(mx1, fmaxf(sa[ns][2], sa[ns][3]));
            }
#pragma unroll
            for (int off = 1; off <= 2; off <<= 1) {
                mx0 = fmaxf(mx0, __shfl_xor_sync(0xffffffffu, mx0, off));
                mx1 = fmaxf(mx1, __shfl_xor_sync(0xffffffffu, mx1, off));
            }
            float mn0 = fmaxf(m0, mx0), mn1 = fmaxf(m1, mx1);
            float al0 = __expf(m0 - mn0), al1 = __expf(m1 - mn1);
            float s0 = 0.f, s1 = 0.f;
#pragma unroll
            for (int ns = 0; ns < 8; ns++) {
                sa[ns][0] = __expf(sa[ns][0] - mn0);
                sa[ns][1] = __expf(sa[ns][1] - mn0);
                sa[ns][2] = __expf(sa[ns][2] - mn1);
                sa[ns][3] = __expf(sa[ns][3] - mn1);
                s0 += sa[ns][0] + sa[ns][1];
                s1 += sa[ns][2] + sa[ns][3];
            }
#pragma unroll
            for (int off = 1; off <= 2; off <<= 1) {
                s0 += __shfl_xor_sync(0xffffffffu, s0, off);
                s1 += __shfl_xor_sync(0xffffffffu, s1, off);
            }
            l0 = l0 * al0 + s0;
            l1 = l1 * al1 + s1;
            m0 = mn0;
            m1 = mn1;
#pragma unroll
            for (int ds = 0; ds < 8; ds++) {
                oacc[ds][0] *= al0;
                oacc[ds][1] *= al0;
                oacc[ds][2] *= al1;
                oacc[ds][3] *= al1;
            }
        }

        uint32_t pf[4][4];
#pragma unroll
        for (int kc = 0; kc < 4; kc++) {
            __half2 h0 = __floats2half2_rn(sa[2 * kc][0], sa[2 * kc][1]);
            __half2 h1 = __floats2half2_rn(sa[2 * kc][2], sa[2 * kc][3]);
            __half2 h2 = __floats2half2_rn(sa[2 * kc + 1][0], sa[2 * kc + 1][1]);
            __half2 h3 = __floats2half2_rn(sa[2 * kc + 1][2], sa[2 * kc + 1][3]);
            pf[kc][0] = *(uint32_t*)&h0;
            pf[kc][1] = *(uint32_t*)&h1;
            pf[kc][2] = *(uint32_t*)&h2;
            pf[kc][3] = *(uint32_t*)&h3;
        }

#pragma unroll
        for (int kc = 0; kc < 4; kc++)
#pragma unroll
            for (int ds2 = 0; ds2 < 4; ds2++) {
                uint32_t vb0, vb1, vb2, vb3;
                uint32_t addr = Vs + (ds2 * 16 * QS_H + kc * 16 + b_off) * 2;
                LDSM_X4(vb0, vb1, vb2, vb3, addr);
                asm volatile(
                    "mma.sync.aligned.m16n8k16.row.col.f32.f16.f16.f32 "
                    "{%0,%1,%2,%3}, {%4,%5,%6,%7}, {%8,%9}, {%0,%1,%2,%3};"
                    : "+f"(oacc[2 * ds2][0]), "+f"(oacc[2 * ds2][1]),
                      "+f"(oacc[2 * ds2][2]), "+f"(oacc[2 * ds2][3])
                    : "r"(pf[kc][0]), "r"(pf[kc][1]), "r"(pf[kc][2]), "r"(pf[kc][3]),
                      "r"(vb0), "r"(vb1));
                asm volatile(
                    "mma.sync.aligned.m16n8k16.row.col.f32.f16.f16.f32 "
                    "{%0,%1,%2,%3}, {%4,%5,%6,%7}, {%8,%9}, {%0,%1,%2,%3};"
                    : "+f"(oacc[2 * ds2 + 1][0]), "+f"(oacc[2 * ds2 + 1][1]),
                      "+f"(oacc[2 * ds2 + 1][2]), "+f"(oacc[2 * ds2 + 1][3])
                    : "r"(pf[kc][0]), "r"(pf[kc][1]), "r"(pf[kc][2]), "r"(pf[kc][3]),
                      "r"(vb2), "r"(vb3));
            }

        __syncthreads();
    }

    const float il0 = 1.f / l0, il1 = 1.f / l1;
    __half* p0 = att + ((size_t)b * Tt + iq * 128 + wr + g) * Cc + h * 64;
    __half* p1 = p0 + 8 * (size_t)Cc;
#pragma unroll
    for (int ds = 0; ds < 8; ds++) {
        *(__half2*)(p0 + ds * 8 + 2 * t) =
            __floats2half2_rn(oacc[ds][0] * il0, oacc[ds][1] * il0);
        *(__half2*)(p1 + ds * 8 + 2 * t) =
            __floats2half2_rn(oacc[ds][2] * il1, oacc[ds][3] * il1);
    }
#undef ISSUE_KV
}

// ---------------------------------------------------------------------------
extern "C" void kernel_launch(void* const* d_in, const int* in_sizes, int n_in,
                              void* d_out, int out_size) {
    const float* x = (const float*)d_in[0];
    const float* Wqkv = (const float*)d_in[1];
    const float* Wout = (const float*)d_in[2];
    float* out = (float*)d_out;

    __half *x16, *wqkvT, *woutT, *qh, *kh, *vt, *att16;
    float* rope;
    cudaGetSymbolAddress((void**)&x16, g_x16);
    cudaGetSymbolAddress((void**)&wqkvT, g_wqkvT);
    cudaGetSymbolAddress((void**)&woutT, g_woutT);
    cudaGetSymbolAddress((void**)&qh, g_qh);
    cudaGetSymbolAddress((void**)&kh, g_kh);
    cudaGetSymbolAddress((void**)&vt, g_vt);
    cudaGetSymbolAddress((void**)&att16, g_att16);
    cudaGetSymbolAddress((void**)&rope, g_rope);

    cudaFuncSetAttribute(hgemm<0>, cudaFuncAttributeMaxDynamicSharedMemorySize,
                         HGEMM_SMEM);
    cudaFuncSetAttribute(hgemm<2>, cudaFuncAttributeMaxDynamicSharedMemorySize,
                         HGEMM_SMEM);
    cudaFuncSetAttribute(flash16, cudaFuncAttributeMaxDynamicSharedMemorySize,
                         FL_SMEM);

    f32_to_f16<<<(BTC / 4 + 255) / 256, 256>>>(x, x16, BTC / 4);
    transpose_to_half<<<dim3(3 * Cc / 32, Cc / 32), dim3(32, 8)>>>(Wqkv, wqkvT,
                                                                   Cc, 3 * Cc);
    transpose_to_half<<<dim3(Cc / 32, Cc / 32), dim3(32, 8)>>>(Wout, woutT, Cc, Cc);
    rope_table_k<<<Tt * 32 / 256, 256>>>(rope);

    // 1) fused: qkv = x16 @ WqkvT^T, RoPE in epilogue, scatter to qh/kh/vt
    hgemm<2><<<dim3(3072 / 128, 8192 / 128), 256, HGEMM_SMEM>>>(
        x16, wqkvT, nullptr, qh, kh, vt, rope, 3072, 1024);
    // 2) fp16 causal flash attention -> att16
    flash16<<<dim3(Tt / 128, Bb * Hh), 256, FL_SMEM>>>(qh, kh, vt, att16);
    // 3) out = att16 @ WoutT^T (fp32 out)
    hgemm<0><<<dim3(1024 / 128, 8192 / 128), 256, HGEMM_SMEM>>>(
        att16, woutT, out, nullptr, nullptr, nullptr, nullptr, 1024, 1024);
}